// round 2
// baseline (speedup 1.0000x reference)
#include <cuda_runtime.h>

#define NN 50000
#define EE 800000
#define CC 128
#define NEG 0.01f

// Scratch (no allocation allowed -> __device__ globals)
__device__ float g_hidden[NN * CC];
__device__ float g_y[NN * CC];
__device__ float g_t[NN * CC];
__device__ float g_aggr[NN * CC];
__device__ float g_delta[NN * 3];
__device__ int   g_is64;   // 1 if edge_index is int64, 0 if int32

typedef unsigned long long u64;

__device__ __forceinline__ u64 pack2(float a, float b) {
    u64 r;
    asm("mov.b64 %0, {%1,%2};" : "=l"(r) : "f"(a), "f"(b));
    return r;
}
__device__ __forceinline__ float2 unpack2(u64 v) {
    float2 f;
    asm("mov.b64 {%0,%1}, %2;" : "=f"(f.x), "=f"(f.y) : "l"(v));
    return f;
}
__device__ __forceinline__ void fma2(u64& d, u64 a, u64 b) {
    asm("fma.rn.f32x2 %0, %1, %2, %0;" : "+l"(d) : "l"(a), "l"(b));
}

__device__ __forceinline__ float leaky(float v) {
    return v >= 0.0f ? v : NEG * v;
}

// ---------------------------------------------------------------------------
// Detect edge_index dtype. Int64 values < 2^31 have zero high words at every
// odd 32-bit position; int32 random indices make that impossible over 1024
// pairs. Deterministic for fixed input.
// ---------------------------------------------------------------------------
__global__ void detect_dtype_kernel(const int* __restrict__ ei32, int n_words)
{
    if (blockIdx.x == 0 && threadIdx.x == 0) {
        int all_hi_zero = 1;
        int pairs = n_words / 2;
        if (pairs > 1024) pairs = 1024;
        for (int p = 0; p < pairs; ++p) {
            if (ei32[2 * p + 1] != 0) { all_hi_zero = 0; break; }
        }
        g_is64 = all_hi_zero;
    }
}

// ---------------------------------------------------------------------------
// Generic fused GEMM: out[M,128] = act(A[M,128] @ W[128,128] + bias) (+ resid)
// CTA tile 128x128, thread tile 8x8 (as 8x4 f32x2 pairs), K chunked by 16.
// act: 0 = none, 1 = leaky
// ---------------------------------------------------------------------------
__global__ __launch_bounds__(256, 2) void gemm128(
    const float* __restrict__ A, const float* __restrict__ W,
    const float* __restrict__ bias, const float* __restrict__ resid,
    float* __restrict__ out, int M, int act)
{
    __shared__ float Ast[16][128];  // transposed A chunk: Ast[kk][row]
    __shared__ float Ws[16][128];   // W chunk: Ws[kk][col]

    const int tid = threadIdx.x;
    const int tx = tid & 15;        // 0..15 -> col group
    const int ty = tid >> 4;        // 0..15 -> row group
    const int row0 = blockIdx.x * 128;

    u64 acc[8][4];
#pragma unroll
    for (int i = 0; i < 8; i++)
#pragma unroll
        for (int j = 0; j < 4; j++) acc[i][j] = 0ull;

    for (int kc = 0; kc < 8; ++kc) {
#pragma unroll
        for (int it = 0; it < 2; ++it) {
            int id = tid + it * 256;
            int r = id >> 2, q = id & 3;
            int grow = row0 + r;
            float4 v = make_float4(0.f, 0.f, 0.f, 0.f);
            if (grow < M)
                v = *(const float4*)(A + (size_t)grow * CC + kc * 16 + q * 4);
            Ast[q * 4 + 0][r] = v.x;
            Ast[q * 4 + 1][r] = v.y;
            Ast[q * 4 + 2][r] = v.z;
            Ast[q * 4 + 3][r] = v.w;
            int kk = id >> 5, nq = id & 31;
            *(float4*)&Ws[kk][nq * 4] =
                *(const float4*)(W + (size_t)(kc * 16 + kk) * CC + nq * 4);
        }
        __syncthreads();

#pragma unroll
        for (int kk = 0; kk < 16; ++kk) {
            const float4 w0 = *(const float4*)&Ws[kk][tx * 8];
            const float4 w1 = *(const float4*)&Ws[kk][tx * 8 + 4];
            u64 wp0 = pack2(w0.x, w0.y);
            u64 wp1 = pack2(w0.z, w0.w);
            u64 wp2 = pack2(w1.x, w1.y);
            u64 wp3 = pack2(w1.z, w1.w);
#pragma unroll
            for (int i = 0; i < 8; i++) {
                float av = Ast[kk][ty * 8 + i];
                u64 a2 = pack2(av, av);
                fma2(acc[i][0], a2, wp0);
                fma2(acc[i][1], a2, wp1);
                fma2(acc[i][2], a2, wp2);
                fma2(acc[i][3], a2, wp3);
            }
        }
        __syncthreads();
    }

    const int gcol = tx * 8;
    const float4 b0 = *(const float4*)(bias + gcol);
    const float4 b1 = *(const float4*)(bias + gcol + 4);
    float bb[8] = {b0.x, b0.y, b0.z, b0.w, b1.x, b1.y, b1.z, b1.w};

#pragma unroll
    for (int i = 0; i < 8; i++) {
        int grow = row0 + ty * 8 + i;
        if (grow >= M) continue;
        float v[8];
#pragma unroll
        for (int j = 0; j < 4; j++) {
            float2 p = unpack2(acc[i][j]);
            v[2 * j + 0] = p.x + bb[2 * j + 0];
            v[2 * j + 1] = p.y + bb[2 * j + 1];
        }
        if (act == 1) {
#pragma unroll
            for (int c = 0; c < 8; c++) v[c] = leaky(v[c]);
        }
        if (resid) {
            const float4 r0 = *(const float4*)(resid + (size_t)grow * CC + gcol);
            const float4 r1 = *(const float4*)(resid + (size_t)grow * CC + gcol + 4);
            v[0] += r0.x; v[1] += r0.y; v[2] += r0.z; v[3] += r0.w;
            v[4] += r1.x; v[5] += r1.y; v[6] += r1.z; v[7] += r1.w;
        }
        *(float4*)(out + (size_t)grow * CC + gcol) = make_float4(v[0], v[1], v[2], v[3]);
        *(float4*)(out + (size_t)grow * CC + gcol + 4) = make_float4(v[4], v[5], v[6], v[7]);
    }
}

// ---------------------------------------------------------------------------
// delta[n] = tanh(hidden[n] @ h_w2 + h_b2), h_w2 is [128,3] row-major.
// One warp per node.
// ---------------------------------------------------------------------------
__global__ void delta_kernel(const float* __restrict__ hidden,
                             const float* __restrict__ h_w2,
                             const float* __restrict__ h_b2,
                             float* __restrict__ delta, int M)
{
    int warp = (blockIdx.x * blockDim.x + threadIdx.x) >> 5;
    int lane = threadIdx.x & 31;
    if (warp >= M) return;
    const float* h = hidden + (size_t)warp * CC;
    float s0 = 0.f, s1 = 0.f, s2 = 0.f;
#pragma unroll
    for (int k = lane; k < CC; k += 32) {
        float hv = h[k];
        s0 += hv * h_w2[k * 3 + 0];
        s1 += hv * h_w2[k * 3 + 1];
        s2 += hv * h_w2[k * 3 + 2];
    }
#pragma unroll
    for (int o = 16; o > 0; o >>= 1) {
        s0 += __shfl_down_sync(0xFFFFFFFFu, s0, o);
        s1 += __shfl_down_sync(0xFFFFFFFFu, s1, o);
        s2 += __shfl_down_sync(0xFFFFFFFFu, s2, o);
    }
    if (lane == 0) {
        delta[warp * 3 + 0] = tanhf(s0 + h_b2[0]);
        delta[warp * 3 + 1] = tanhf(s1 + h_b2[1]);
        delta[warp * 3 + 2] = tanhf(s2 + h_b2[2]);
    }
}

__global__ void zero_kernel(float4* __restrict__ p, int n4)
{
    int i = blockIdx.x * blockDim.x + threadIdx.x;
    if (i < n4) p[i] = make_float4(0.f, 0.f, 0.f, 0.f);
}

// ---------------------------------------------------------------------------
// Edge kernel. One warp per edge:
//   rel = pos[src] - pos[dst] + delta[dst]
//   z   = y[src] + rel @ f_w[0:3]
//   aggr[dst] += leaky(z)   via red.global.add.v4.f32
// Indices read per g_is64 flag; out-of-range indices skipped (safety).
// ---------------------------------------------------------------------------
__global__ __launch_bounds__(256) void edge_kernel(
    const void* __restrict__ ei_raw, const float* __restrict__ pos,
    const float* __restrict__ delta, const float* __restrict__ y,
    const float* __restrict__ f_w, float* __restrict__ aggr, int E, int M)
{
    int e = (blockIdx.x * 256 + threadIdx.x) >> 5;
    int lane = threadIdx.x & 31;
    if (e >= E) return;

    int j, i;
    if (g_is64) {
        const long long* ei = (const long long*)ei_raw;
        j = (int)ei[e];
        i = (int)ei[E + e];
    } else {
        const int* ei = (const int*)ei_raw;
        j = ei[e];
        i = ei[E + e];
    }
    if ((unsigned)j >= (unsigned)M || (unsigned)i >= (unsigned)M) return;

    float r0 = pos[j * 3 + 0] - pos[i * 3 + 0] + delta[i * 3 + 0];
    float r1 = pos[j * 3 + 1] - pos[i * 3 + 1] + delta[i * 3 + 1];
    float r2 = pos[j * 3 + 2] - pos[i * 3 + 2] + delta[i * 3 + 2];

    int c = lane * 4;
    float4 yv = *(const float4*)(y + (size_t)j * CC + c);
    float4 w0 = *(const float4*)(f_w + 0 * CC + c);
    float4 w1 = *(const float4*)(f_w + 1 * CC + c);
    float4 w2 = *(const float4*)(f_w + 2 * CC + c);

    float4 z;
    z.x = leaky(yv.x + r0 * w0.x + r1 * w1.x + r2 * w2.x);
    z.y = leaky(yv.y + r0 * w0.y + r1 * w1.y + r2 * w2.y);
    z.z = leaky(yv.z + r0 * w0.z + r1 * w1.z + r2 * w2.z);
    z.w = leaky(yv.w + r0 * w0.w + r1 * w1.w + r2 * w2.w);

    float* dst = aggr + (size_t)i * CC + c;
    asm volatile("red.global.add.v4.f32 [%0], {%1,%2,%3,%4};"
                 :: "l"(dst), "f"(z.x), "f"(z.y), "f"(z.z), "f"(z.w)
                 : "memory");
}

// ---------------------------------------------------------------------------
extern "C" void kernel_launch(void* const* d_in, const int* in_sizes, int n_in,
                              void* d_out, int out_size)
{
    const float* x      = (const float*)d_in[0];
    const float* pos    = (const float*)d_in[1];
    const void*  ei     = d_in[2];
    const float* h_w1   = (const float*)d_in[3];
    const float* h_b1   = (const float*)d_in[4];
    const float* h_w2   = (const float*)d_in[5];
    const float* h_b2   = (const float*)d_in[6];
    const float* f_w    = (const float*)d_in[7];
    const float* f_b    = (const float*)d_in[8];
    const float* g_w1   = (const float*)d_in[9];
    const float* g_b1   = (const float*)d_in[10];
    const float* g_w2   = (const float*)d_in[11];
    const float* g_b2   = (const float*)d_in[12];
    float* out = (float*)d_out;

    const int M = in_sizes[0] / CC;  // 50000
    const int E = in_sizes[2] / 2;   // 800000 (element count same for i32/i64)

    float *hidden, *y, *t, *aggr, *delta;
    cudaGetSymbolAddress((void**)&hidden, g_hidden);
    cudaGetSymbolAddress((void**)&y,      g_y);
    cudaGetSymbolAddress((void**)&t,      g_t);
    cudaGetSymbolAddress((void**)&aggr,   g_aggr);
    cudaGetSymbolAddress((void**)&delta,  g_delta);

    const int gcta = (M + 127) / 128;

    // detect int32 vs int64 edge_index (deterministic)
    detect_dtype_kernel<<<1, 32>>>((const int*)ei, 2048);
    // hidden = leaky(x @ h_w1 + h_b1)
    gemm128<<<gcta, 256>>>(x, h_w1, h_b1, nullptr, hidden, M, 1);
    // y = x @ f_w[3:, :] + f_b   (leaky deferred to edge kernel)
    gemm128<<<gcta, 256>>>(x, f_w + 3 * CC, f_b, nullptr, y, M, 0);
    // delta = tanh(hidden @ h_w2 + h_b2)
    delta_kernel<<<(M * 32 + 255) / 256, 256>>>(hidden, h_w2, h_b2, delta, M);
    // aggr = 0
    zero_kernel<<<(M * CC / 4 + 255) / 256, 256>>>((float4*)aggr, M * CC / 4);
    // edge messages + scatter-add
    edge_kernel<<<(E + 7) / 8, 256>>>(ei, pos, delta, y, f_w, aggr, E, M);
    // t = leaky(aggr @ g_w1 + g_b1)
    gemm128<<<gcta, 256>>>(aggr, g_w1, g_b1, nullptr, t, M, 1);
    // out = t @ g_w2 + g_b2 + x
    gemm128<<<gcta, 256>>>(t, g_w2, g_b2, x, out, M, 0);
}

// round 4
// speedup vs baseline: 1.2675x; 1.2675x over previous
#include <cuda_runtime.h>
#include <cuda_bf16.h>
#include <cstdint>

#define NN 50000
#define EE 800000
#define CC 128
#define NEG 0.01f

// Scratch (no allocation allowed -> __device__ globals)
__device__ float g_hidden[NN * CC];
__device__ float g_y[NN * CC];
__device__ float g_t[NN * CC];
__device__ float g_aggr[NN * CC];
__device__ float g_delta[NN * 3];
__device__ int   g_is64;
// Padded transposed bf16 weight images: Wt[n][k], row stride 136 bf16 (272B).
// 4 matrices x 128 rows x 272B = 34816 B each.
#define WTILE_B 34816
__device__ unsigned char g_Whi[4 * WTILE_B];
__device__ unsigned char g_Wlo[4 * WTILE_B];

__device__ __forceinline__ float leaky(float v) {
    return v >= 0.0f ? v : NEG * v;
}

// ---------------------------------------------------------------------------
// Detect edge_index dtype (int64 vs int32).
// ---------------------------------------------------------------------------
__global__ void detect_dtype_kernel(const int* __restrict__ ei32, int n_words)
{
    if (blockIdx.x == 0 && threadIdx.x == 0) {
        int all_hi_zero = 1;
        int pairs = n_words / 2;
        if (pairs > 1024) pairs = 1024;
        for (int p = 0; p < pairs; ++p) {
            if (ei32[2 * p + 1] != 0) { all_hi_zero = 0; break; }
        }
        g_is64 = all_hi_zero;
    }
}

// ---------------------------------------------------------------------------
// Prep: split W (128x128 f32, W[k][n]) into bf16 hi/lo, write transposed
// padded images Wt[n][k] with 272B row stride.
// ---------------------------------------------------------------------------
__global__ void prep_weights_kernel(const float* __restrict__ w0,
                                    const float* __restrict__ w1,
                                    const float* __restrict__ w2,
                                    const float* __restrict__ w3)
{
    int idx = blockIdx.x * 256 + threadIdx.x;   // 4*16384 total
    if (idx >= 4 * 16384) return;
    int m = idx >> 14;
    int rem = idx & 16383;
    int k = rem >> 7;      // 0..127
    int n = rem & 127;     // 0..127
    const float* w = (m == 0) ? w0 : (m == 1) ? w1 : (m == 2) ? w2 : w3;
    float v = w[k * CC + n];
    __nv_bfloat16 hi = __float2bfloat16(v);
    __nv_bfloat16 lo = __float2bfloat16(v - __bfloat162float(hi));
    uint32_t off = (uint32_t)m * WTILE_B + (uint32_t)n * 272u + (uint32_t)k * 2u;
    *(__nv_bfloat16*)(g_Whi + off) = hi;
    *(__nv_bfloat16*)(g_Wlo + off) = lo;
}

// ---------------------------------------------------------------------------
// mma.sync m16n8k16 bf16 (portable PTX, sm_80+)
// ---------------------------------------------------------------------------
__device__ __forceinline__ void mma_bf16(float* c, const uint32_t* a, const uint32_t* b)
{
    asm volatile(
        "mma.sync.aligned.m16n8k16.row.col.f32.bf16.bf16.f32 "
        "{%0,%1,%2,%3}, {%4,%5,%6,%7}, {%8,%9}, {%0,%1,%2,%3};"
        : "+f"(c[0]), "+f"(c[1]), "+f"(c[2]), "+f"(c[3])
        : "r"(a[0]), "r"(a[1]), "r"(a[2]), "r"(a[3]), "r"(b[0]), "r"(b[1]));
}

__device__ __forceinline__ void cvt_hilo(float2 f, uint32_t& hi, uint32_t& lo)
{
    __nv_bfloat16 hx = __float2bfloat16(f.x);
    __nv_bfloat16 hy = __float2bfloat16(f.y);
    __nv_bfloat16 lx = __float2bfloat16(f.x - __bfloat162float(hx));
    __nv_bfloat16 ly = __float2bfloat16(f.y - __bfloat162float(hy));
    hi = (uint32_t)__bfloat16_as_ushort(hx) | ((uint32_t)__bfloat16_as_ushort(hy) << 16);
    lo = (uint32_t)__bfloat16_as_ushort(lx) | ((uint32_t)__bfloat16_as_ushort(ly) << 16);
}

// ---------------------------------------------------------------------------
// Tensor-core GEMM: out[M,128] = act(A[M,128] @ W[128,128] + bias) (+resid)
// Split-bf16 3-product: D = Ahi@Whi + Ahi@Wlo + Alo@Whi  (fp32 accum).
// CTA: 256 threads / 8 warps, 128 rows x 128 cols. A staged fp32 in smem;
// per-fragment conversion to bf16 hi/lo. W tiles copied pre-swizzled.
// smem: A[0,67584) stride 132 f32; Whi[67584,+34816); Wlo[...]; bias 512B.
// ---------------------------------------------------------------------------
#define SM_A    0
#define SM_WHI  67584
#define SM_WLO  102400
#define SM_BIAS 137216
#define SM_TOT  137728

__global__ __launch_bounds__(256) void gemm_mma(
    const float* __restrict__ A,
    const unsigned char* __restrict__ Whi, const unsigned char* __restrict__ Wlo,
    const float* __restrict__ bias, const float* __restrict__ resid,
    float* __restrict__ out, int M, int act)
{
    extern __shared__ char sm[];
    float* sA = (float*)(sm + SM_A);                 // [128][132]
    const int tid = threadIdx.x;

    // Copy W tiles (verbatim byte image) + bias
    {
        const uint4* sh = (const uint4*)Whi;
        const uint4* sl = (const uint4*)Wlo;
        uint4* dh = (uint4*)(sm + SM_WHI);
        uint4* dl = (uint4*)(sm + SM_WLO);
#pragma unroll
        for (int i = tid; i < WTILE_B / 16; i += 256) {
            dh[i] = sh[i];
            dl[i] = sl[i];
        }
        if (tid < 128) ((float*)(sm + SM_BIAS))[tid] = bias[tid];
    }

    // Stage A tile as fp32
    {
        int row = tid & 127, kh = (tid >> 7) * 64;
        int grow = blockIdx.x * 128 + row;
        const float4* src = (grow < M) ? (const float4*)(A + (size_t)grow * CC + kh) : nullptr;
        float* dst = sA + row * 132 + kh;
#pragma unroll
        for (int i = 0; i < 16; i++) {
            float4 v = src ? src[i] : make_float4(0.f, 0.f, 0.f, 0.f);
            *(float4*)(dst + i * 4) = v;
        }
    }
    __syncthreads();

    const int warp = tid >> 5, lane = tid & 31;
    const int g = lane >> 2, q = lane & 3;
    const int r0 = warp * 16;

    float acc[16][4];
#pragma unroll
    for (int ct = 0; ct < 16; ct++)
#pragma unroll
        for (int c = 0; c < 4; c++) acc[ct][c] = 0.f;

    const float* a0p = sA + (r0 + g) * 132;
    const float* a1p = sA + (r0 + g + 8) * 132;
    const uint32_t* whp = (const uint32_t*)(sm + SM_WHI);
    const uint32_t* wlp = (const uint32_t*)(sm + SM_WLO);

#pragma unroll
    for (int kc = 0; kc < 8; kc++) {
        const int k0 = kc * 16 + q * 2;
        float2 f00 = *(const float2*)(a0p + k0);
        float2 f10 = *(const float2*)(a1p + k0);
        float2 f01 = *(const float2*)(a0p + k0 + 8);
        float2 f11 = *(const float2*)(a1p + k0 + 8);
        uint32_t ahi[4], alo[4];
        cvt_hilo(f00, ahi[0], alo[0]);
        cvt_hilo(f10, ahi[1], alo[1]);
        cvt_hilo(f01, ahi[2], alo[2]);
        cvt_hilo(f11, ahi[3], alo[3]);

#pragma unroll
        for (int ct = 0; ct < 16; ct++) {
            int col = ct * 8 + g;
            const uint32_t* ph = whp + col * 68 + kc * 8;
            const uint32_t* pl = wlp + col * 68 + kc * 8;
            uint32_t bh[2] = { ph[q], ph[q + 4] };
            uint32_t bl[2] = { pl[q], pl[q + 4] };
            mma_bf16(acc[ct], ahi, bh);
            mma_bf16(acc[ct], ahi, bl);
            mma_bf16(acc[ct], alo, bh);
        }
    }

    // Epilogue
    const float* sbias = (const float*)(sm + SM_BIAS);
    int orow0 = blockIdx.x * 128 + r0 + g;
    int orow1 = orow0 + 8;
#pragma unroll
    for (int ct = 0; ct < 16; ct++) {
        int col = ct * 8 + q * 2;
        float b0 = sbias[col], b1 = sbias[col + 1];
        float v00 = acc[ct][0] + b0, v01 = acc[ct][1] + b1;
        float v10 = acc[ct][2] + b0, v11 = acc[ct][3] + b1;
        if (act == 1) {
            v00 = leaky(v00); v01 = leaky(v01);
            v10 = leaky(v10); v11 = leaky(v11);
        }
        if (orow0 < M) {
            if (resid) {
                float2 r = *(const float2*)(resid + (size_t)orow0 * CC + col);
                v00 += r.x; v01 += r.y;
            }
            *(float2*)(out + (size_t)orow0 * CC + col) = make_float2(v00, v01);
        }
        if (orow1 < M) {
            if (resid) {
                float2 r = *(const float2*)(resid + (size_t)orow1 * CC + col);
                v10 += r.x; v11 += r.y;
            }
            *(float2*)(out + (size_t)orow1 * CC + col) = make_float2(v10, v11);
        }
    }
}

// ---------------------------------------------------------------------------
// delta[n] = tanh(hidden[n] @ h_w2 + h_b2)
// ---------------------------------------------------------------------------
__global__ void delta_kernel(const float* __restrict__ hidden,
                             const float* __restrict__ h_w2,
                             const float* __restrict__ h_b2,
                             float* __restrict__ delta, int M)
{
    int warp = (blockIdx.x * blockDim.x + threadIdx.x) >> 5;
    int lane = threadIdx.x & 31;
    if (warp >= M) return;
    const float* h = hidden + (size_t)warp * CC;
    float s0 = 0.f, s1 = 0.f, s2 = 0.f;
#pragma unroll
    for (int k = lane; k < CC; k += 32) {
        float hv = h[k];
        s0 += hv * h_w2[k * 3 + 0];
        s1 += hv * h_w2[k * 3 + 1];
        s2 += hv * h_w2[k * 3 + 2];
    }
#pragma unroll
    for (int o = 16; o > 0; o >>= 1) {
        s0 += __shfl_down_sync(0xFFFFFFFFu, s0, o);
        s1 += __shfl_down_sync(0xFFFFFFFFu, s1, o);
        s2 += __shfl_down_sync(0xFFFFFFFFu, s2, o);
    }
    if (lane == 0) {
        delta[warp * 3 + 0] = tanhf(s0 + h_b2[0]);
        delta[warp * 3 + 1] = tanhf(s1 + h_b2[1]);
        delta[warp * 3 + 2] = tanhf(s2 + h_b2[2]);
    }
}

__global__ void zero_kernel(float4* __restrict__ p, int n4)
{
    int i = blockIdx.x * blockDim.x + threadIdx.x;
    if (i < n4) p[i] = make_float4(0.f, 0.f, 0.f, 0.f);
}

// ---------------------------------------------------------------------------
// Edge kernel: one warp per edge; scatter-add via red.global.add.v4.f32
// ---------------------------------------------------------------------------
__global__ __launch_bounds__(256) void edge_kernel(
    const void* __restrict__ ei_raw, const float* __restrict__ pos,
    const float* __restrict__ delta, const float* __restrict__ y,
    const float* __restrict__ f_w, float* __restrict__ aggr, int E, int M)
{
    int e = (blockIdx.x * 256 + threadIdx.x) >> 5;
    int lane = threadIdx.x & 31;
    if (e >= E) return;

    int j, i;
    if (g_is64) {
        const long long* ei = (const long long*)ei_raw;
        j = (int)ei[e];
        i = (int)ei[E + e];
    } else {
        const int* ei = (const int*)ei_raw;
        j = ei[e];
        i = ei[E + e];
    }
    if ((unsigned)j >= (unsigned)M || (unsigned)i >= (unsigned)M) return;

    float r0 = pos[j * 3 + 0] - pos[i * 3 + 0] + delta[i * 3 + 0];
    float r1 = pos[j * 3 + 1] - pos[i * 3 + 1] + delta[i * 3 + 1];
    float r2 = pos[j * 3 + 2] - pos[i * 3 + 2] + delta[i * 3 + 2];

    int c = lane * 4;
    float4 yv = *(const float4*)(y + (size_t)j * CC + c);
    float4 w0 = *(const float4*)(f_w + 0 * CC + c);
    float4 w1 = *(const float4*)(f_w + 1 * CC + c);
    float4 w2 = *(const float4*)(f_w + 2 * CC + c);

    float4 z;
    z.x = leaky(yv.x + r0 * w0.x + r1 * w1.x + r2 * w2.x);
    z.y = leaky(yv.y + r0 * w0.y + r1 * w1.y + r2 * w2.y);
    z.z = leaky(yv.z + r0 * w0.z + r1 * w1.z + r2 * w2.z);
    z.w = leaky(yv.w + r0 * w0.w + r1 * w1.w + r2 * w2.w);

    float* dst = aggr + (size_t)i * CC + c;
    asm volatile("red.global.add.v4.f32 [%0], {%1,%2,%3,%4};"
                 :: "l"(dst), "f"(z.x), "f"(z.y), "f"(z.z), "f"(z.w)
                 : "memory");
}

// ---------------------------------------------------------------------------
extern "C" void kernel_launch(void* const* d_in, const int* in_sizes, int n_in,
                              void* d_out, int out_size)
{
    const float* x      = (const float*)d_in[0];
    const float* pos    = (const float*)d_in[1];
    const void*  ei     = d_in[2];
    const float* h_w1   = (const float*)d_in[3];
    const float* h_b1   = (const float*)d_in[4];
    const float* h_w2   = (const float*)d_in[5];
    const float* h_b2   = (const float*)d_in[6];
    const float* f_w    = (const float*)d_in[7];
    const float* f_b    = (const float*)d_in[8];
    const float* g_w1   = (const float*)d_in[9];
    const float* g_b1   = (const float*)d_in[10];
    const float* g_w2   = (const float*)d_in[11];
    const float* g_b2   = (const float*)d_in[12];
    float* out = (float*)d_out;

    const int M = in_sizes[0] / CC;  // 50000
    const int E = in_sizes[2] / 2;   // 800000

    float *hidden, *y, *t, *aggr, *delta;
    unsigned char *Whi, *Wlo;
    cudaGetSymbolAddress((void**)&hidden, g_hidden);
    cudaGetSymbolAddress((void**)&y,      g_y);
    cudaGetSymbolAddress((void**)&t,      g_t);
    cudaGetSymbolAddress((void**)&aggr,   g_aggr);
    cudaGetSymbolAddress((void**)&delta,  g_delta);
    cudaGetSymbolAddress((void**)&Whi,    g_Whi);
    cudaGetSymbolAddress((void**)&Wlo,    g_Wlo);

    static int smem_set = 0;
    if (!smem_set) {
        cudaFuncSetAttribute(gemm_mma, cudaFuncAttributeMaxDynamicSharedMemorySize, SM_TOT);
        smem_set = 1;
    }

    const int gcta = (M + 127) / 128;

    // dtype detect + weight prep (deterministic every call)
    detect_dtype_kernel<<<1, 32>>>((const int*)ei, 2048);
    prep_weights_kernel<<<(4 * 16384 + 255) / 256, 256>>>(h_w1, f_w + 3 * CC, g_w1, g_w2);

    // hidden = leaky(x @ h_w1 + h_b1)
    gemm_mma<<<gcta, 256, SM_TOT>>>(x, Whi + 0 * WTILE_B, Wlo + 0 * WTILE_B, h_b1, nullptr, hidden, M, 1);
    // y = x @ f_w[3:, :] + f_b   (leaky deferred to edge kernel)
    gemm_mma<<<gcta, 256, SM_TOT>>>(x, Whi + 1 * WTILE_B, Wlo + 1 * WTILE_B, f_b, nullptr, y, M, 0);
    // delta = tanh(hidden @ h_w2 + h_b2)
    delta_kernel<<<(M * 32 + 255) / 256, 256>>>(hidden, h_w2, h_b2, delta, M);
    // aggr = 0
    zero_kernel<<<(M * CC / 4 + 255) / 256, 256>>>((float4*)aggr, M * CC / 4);
    // edge messages + scatter-add
    edge_kernel<<<(E + 7) / 8, 256>>>(ei, pos, delta, y, f_w, aggr, E, M);
    // t = leaky(aggr @ g_w1 + g_b1)
    gemm_mma<<<gcta, 256, SM_TOT>>>(aggr, Whi + 2 * WTILE_B, Wlo + 2 * WTILE_B, g_b1, nullptr, t, M, 1);
    // out = t @ g_w2 + g_b2 + x
    gemm_mma<<<gcta, 256, SM_TOT>>>(t, Whi + 3 * WTILE_B, Wlo + 3 * WTILE_B, g_b2, x, out, M, 0);
}